// round 15
// baseline (speedup 1.0000x reference)
#include <cuda_runtime.h>
#include <cuda_fp16.h>
#include <cstdint>

// BMM_S8T_S8N_F16T two-phase:
//  1) pack kernel: int32 -> int8 packed scratch
//  2) main kernel: persistent (444 CTAs, 3/SM), cp.async double-buffered
//     swizzled tiles; per 16-row warp slab: IMMA cols 0..39 (ldmatrix),
//     dp4a cols 40..63.
// out[b,m,n] = f32( fp16_round( alpha * sum_k a[b,m,k]*b[b,n,k] ) )

#define BATCH 64
#define MDIM 1024
#define NDIM 1024
#define KDIM 128
#define NTILES 8192          // 16 x 8 x 64
#define NCTAS 444            // 3 per SM

#define BM 128
#define BN 64
#define NI_MMA 5             // IMMA cols 0..39
#define COL_DP 40            // dp4a cols 40..63
#define NI_DP 3

__device__ uint4 g_Apack[(size_t)BATCH * MDIM * 8];
__device__ uint4 g_Bpack[(size_t)BATCH * NDIM * 8];

#define PACK4(v) __byte_perm(__byte_perm((v).x, (v).y, 0x0040), \
                             __byte_perm((v).z, (v).w, 0x0040), 0x5410)

static __device__ __forceinline__ uint32_t smem_u32(const void* p) {
    return (uint32_t)__cvta_generic_to_shared(p);
}

// ---------------- Pre-pass: pack int32 -> int8 ----------------
__global__ __launch_bounds__(256)
void pack_kernel(const int* __restrict__ A, const int* __restrict__ Bmat) {
    const int idx = blockIdx.x * 256 + threadIdx.x;
    const size_t base = (size_t)idx * 16;

    uint4 pa;
    {
        int4 v0 = *(const int4*)(A + base);
        int4 v1 = *(const int4*)(A + base + 4);
        int4 v2 = *(const int4*)(A + base + 8);
        int4 v3 = *(const int4*)(A + base + 12);
        pa.x = PACK4(v0); pa.y = PACK4(v1); pa.z = PACK4(v2); pa.w = PACK4(v3);
    }
    g_Apack[idx] = pa;

    uint4 pb;
    {
        int4 v0 = *(const int4*)(Bmat + base);
        int4 v1 = *(const int4*)(Bmat + base + 4);
        int4 v2 = *(const int4*)(Bmat + base + 8);
        int4 v3 = *(const int4*)(Bmat + base + 12);
        pb.x = PACK4(v0); pb.y = PACK4(v1); pb.z = PACK4(v2); pb.w = PACK4(v3);
    }
    g_Bpack[idx] = pb;
}

// ---------------- Main kernel ----------------
// Tile layout: 32 words (128B) per row, granule (16B) swizzled: g' = g ^ (row&7).
__global__ __launch_bounds__(256, 3)
void bmm_s8_main_kernel(const float* __restrict__ alpha_p,
                        float* __restrict__ Out) {
    __shared__ __align__(16) uint32_t As[2][BM * 32];   // 2 x 16 KB
    __shared__ __align__(16) uint32_t Bs[2][BN * 32];   // 2 x  8 KB

    const int tid  = threadIdx.x;
    const int lane = tid & 31;
    const int wid  = tid >> 5;

    const float alpha = *alpha_p;

    const int rb = wid * 16;
    const int lr = lane & 3;
    const int lq = lane >> 2;
    const int g  = lane >> 3;    // dp4a row interleave 0..3
    const int j  = lane & 7;     // dp4a col interleave 0..7

    // ---- cp.async tile issue (per thread: 4 A granules + 2 B granules) ----
    #define ISSUE_TILE(T, B_) do {                                              \
        const int bn_ = (T) & 15, bm_ = ((T) >> 4) & 7, bz_ = (T) >> 7;         \
        const uint4* Ab_ = g_Apack + ((size_t)bz_ * MDIM + bm_ * BM) * 8;       \
        _Pragma("unroll")                                                       \
        for (int i = 0; i < 4; i++) {                                           \
            int idx = tid + i * 256;                                            \
            int row = idx >> 3, gr = idx & 7;                                   \
            uint32_t dst = smem_u32(&As[B_][row * 32 + ((gr ^ (row & 7)) << 2)]);\
            asm volatile("cp.async.cg.shared.global [%0], [%1], 16;"            \
                         :: "r"(dst), "l"(Ab_ + row * 8 + gr) : "memory");      \
        }                                                                       \
        const uint4* Bb_ = g_Bpack + ((size_t)bz_ * NDIM + bn_ * BN) * 8;       \
        _Pragma("unroll")                                                       \
        for (int i = 0; i < 2; i++) {                                           \
            int idx = tid + i * 256;                                            \
            int row = idx >> 3, gr = idx & 7;                                   \
            uint32_t dst = smem_u32(&Bs[B_][row * 32 + ((gr ^ (row & 7)) << 2)]);\
            asm volatile("cp.async.cg.shared.global [%0], [%1], 16;"            \
                         :: "r"(dst), "l"(Bb_ + row * 8 + gr) : "memory");      \
        }                                                                       \
    } while (0)

    // ---- ldmatrix per-lane constants ----
    const int a_row  = rb + (lane & 15);
    const int a_sw   = a_row & 7;
    const int a_hi   = (lane >> 4) & 1;
    const int b_row0 = (lane & 7) + ((lane & 16) ? 8 : 0);   // p-block base row
    const int b_sw   = lane & 7;
    const int b_hi   = (lane >> 3) & 1;
    const int b_row2 = 32 + (lane & 7);                      // x2 block rows

    int t = blockIdx.x;
    int buf = 0;

    ISSUE_TILE(t, 0);
    asm volatile("cp.async.commit_group;" ::: "memory");

    while (t < NTILES) {
        const int tn = t + NCTAS;
        if (tn < NTILES) ISSUE_TILE(tn, buf ^ 1);
        asm volatile("cp.async.commit_group;" ::: "memory");
        asm volatile("cp.async.wait_group 1;" ::: "memory");
        __syncthreads();                       // tile t ready in buf

        const uint32_t sA = smem_u32(&As[buf][0]);
        const uint32_t sB = smem_u32(&Bs[buf][0]);

        int macc[NI_MMA][4];
        #pragma unroll
        for (int ni = 0; ni < NI_MMA; ni++)
            #pragma unroll
            for (int r = 0; r < 4; r++) macc[ni][r] = 0;

        int dacc[4][NI_DP];
        #pragma unroll
        for (int mi = 0; mi < 4; mi++)
            #pragma unroll
            for (int ni = 0; ni < NI_DP; ni++) dacc[mi][ni] = 0;

        #pragma unroll
        for (int ks = 0; ks < 4; ks++) {
            // --- IMMA: cols 0..39 ---
            uint32_t af[4];
            {
                uint32_t addr = sA + a_row * 128 + (((2 * ks + a_hi) ^ a_sw) << 4);
                asm volatile("ldmatrix.sync.aligned.m8n8.x4.shared.b16 {%0,%1,%2,%3}, [%4];"
                             : "=r"(af[0]), "=r"(af[1]), "=r"(af[2]), "=r"(af[3])
                             : "r"(addr));
            }
            #pragma unroll
            for (int p = 0; p < 2; p++) {
                uint32_t bf[4];
                uint32_t addr = sB + (b_row0 + p * 16) * 128
                              + (((2 * ks + b_hi) ^ b_sw) << 4);
                asm volatile("ldmatrix.sync.aligned.m8n8.x4.shared.b16 {%0,%1,%2,%3}, [%4];"
                             : "=r"(bf[0]), "=r"(bf[1]), "=r"(bf[2]), "=r"(bf[3])
                             : "r"(addr));
                #pragma unroll
                for (int h = 0; h < 2; h++) {
                    int ni = p * 2 + h;
                    asm volatile(
                        "mma.sync.aligned.m16n8k32.row.col.s32.s8.s8.s32 "
                        "{%0,%1,%2,%3}, {%4,%5,%6,%7}, {%8,%9}, {%0,%1,%2,%3};"
                        : "+r"(macc[ni][0]), "+r"(macc[ni][1]),
                          "+r"(macc[ni][2]), "+r"(macc[ni][3])
                        : "r"(af[0]), "r"(af[1]), "r"(af[2]), "r"(af[3]),
                          "r"(bf[h * 2]), "r"(bf[h * 2 + 1]));
                }
            }
            {
                uint32_t bf[2];
                uint32_t addr = sB + b_row2 * 128 + (((2 * ks + b_hi) ^ b_sw) << 4);
                asm volatile("ldmatrix.sync.aligned.m8n8.x2.shared.b16 {%0,%1}, [%2];"
                             : "=r"(bf[0]), "=r"(bf[1]) : "r"(addr));
                asm volatile(
                    "mma.sync.aligned.m16n8k32.row.col.s32.s8.s8.s32 "
                    "{%0,%1,%2,%3}, {%4,%5,%6,%7}, {%8,%9}, {%0,%1,%2,%3};"
                    : "+r"(macc[4][0]), "+r"(macc[4][1]),
                      "+r"(macc[4][2]), "+r"(macc[4][3])
                    : "r"(af[0]), "r"(af[1]), "r"(af[2]), "r"(af[3]),
                      "r"(bf[0]), "r"(bf[1]));
            }

            // --- dp4a: cols 40..63 ---
            #pragma unroll
            for (int c = 0; c < 2; c++) {
                const int gr = ks * 2 + c;
                uint4 av[4];
                #pragma unroll
                for (int mi = 0; mi < 4; mi++) {
                    int row = rb + g + 4 * mi;
                    av[mi] = *(const uint4*)&As[buf][row * 32 + ((gr ^ (row & 7)) << 2)];
                }
                #pragma unroll
                for (int ni = 0; ni < NI_DP; ni++) {
                    int cc = COL_DP + j + 8 * ni;
                    uint4 bv = *(const uint4*)&Bs[buf][cc * 32 + ((gr ^ j) << 2)];
                    #pragma unroll
                    for (int mi = 0; mi < 4; mi++) {
                        int v = dacc[mi][ni];
                        v = __dp4a((int)av[mi].x, (int)bv.x, v);
                        v = __dp4a((int)av[mi].y, (int)bv.y, v);
                        v = __dp4a((int)av[mi].z, (int)bv.z, v);
                        v = __dp4a((int)av[mi].w, (int)bv.w, v);
                        dacc[mi][ni] = v;
                    }
                }
            }
        }

        // ---- Epilogue ----
        {
            const int bn = t & 15, bm = (t >> 4) & 7, bz = t >> 7;
            float* obase = Out + ((size_t)bz * MDIM + bm * BM) * NDIM + bn * BN;

            #pragma unroll
            for (int ni = 0; ni < NI_MMA; ni++) {
                int c0 = ni * 8 + lr * 2;
                float2 v0;
                v0.x = __half2float(__float2half_rn(alpha * (float)macc[ni][0]));
                v0.y = __half2float(__float2half_rn(alpha * (float)macc[ni][1]));
                *(float2*)(obase + (size_t)(rb + lq) * NDIM + c0) = v0;
                float2 v1;
                v1.x = __half2float(__float2half_rn(alpha * (float)macc[ni][2]));
                v1.y = __half2float(__float2half_rn(alpha * (float)macc[ni][3]));
                *(float2*)(obase + (size_t)(rb + lq + 8) * NDIM + c0) = v1;
            }
            #pragma unroll
            for (int mi = 0; mi < 4; mi++) {
                float* orow = obase + (size_t)(rb + g + 4 * mi) * NDIM;
                #pragma unroll
                for (int ni = 0; ni < NI_DP; ni++) {
                    int col = COL_DP + j + 8 * ni;
                    orow[col] = __half2float(__float2half_rn(alpha * (float)dacc[mi][ni]));
                }
            }
        }

        __syncthreads();     // all reads of buf done before it is refilled
        buf ^= 1;
        t = tn;
    }
    #undef ISSUE_TILE
}

extern "C" void kernel_launch(void* const* d_in, const int* in_sizes, int n_in,
                              void* d_out, int out_size) {
    // alpha is the size-1 input; the two large tensors are a then b in index order.
    int ai = -1, bi = -1, si = -1;
    for (int i = 0; i < n_in; i++) {
        if (in_sizes[i] == 1) { si = i; }
        else if (ai < 0)      { ai = i; }
        else                  { bi = i; }
    }
    const int*   a     = (const int*)d_in[ai];
    const int*   b     = (const int*)d_in[bi];
    const float* alpha = (const float*)d_in[si];
    float*       out   = (float*)d_out;

    pack_kernel<<<2048, 256>>>(a, b);
    bmm_s8_main_kernel<<<NCTAS, 256>>>(alpha, out);
}

// round 16
// speedup vs baseline: 1.0734x; 1.0734x over previous
#include <cuda_runtime.h>
#include <cuda_fp16.h>
#include <cstdint>

// BMM_S8T_S8N_F16T two-phase:
//  1) pack kernel: int32 inputs -> int8 packed scratch (static __device__)
//  2) main kernel: occ-3 hybrid, CTA tile 128x64; per 16-row warp slab:
//     IMMA cols 0..39 (ldmatrix fragment loads), dp4a cols 40..63.
//     NEW: odd warps run dp4a-then-IMMA per k-step (phase staggering) so the
//     tensor and fma/alu pipes are fed concurrently across the SM.
// out[b,m,n] = f32( fp16_round( alpha * sum_k a[b,m,k]*b[b,n,k] ) )

#define BATCH 64
#define MDIM 1024
#define NDIM 1024
#define KDIM 128

#define BM 128
#define BN 64
#define ROWSTRIDE 36       // 32 k-words + 4 pad -> conflict-free banks

#define NI_MMA 5           // IMMA cols 0..39
#define COL_DP 40          // dp4a cols 40..63
#define NI_DP 3

__device__ uint4 g_Apack[(size_t)BATCH * MDIM * 8];
__device__ uint4 g_Bpack[(size_t)BATCH * NDIM * 8];

#define PACK4(v) __byte_perm(__byte_perm((v).x, (v).y, 0x0040), \
                             __byte_perm((v).z, (v).w, 0x0040), 0x5410)

static __device__ __forceinline__ uint32_t smem_u32(const void* p) {
    return (uint32_t)__cvta_generic_to_shared(p);
}

// ---------------- Pre-pass: pack int32 -> int8 ----------------
__global__ __launch_bounds__(256)
void pack_kernel(const int* __restrict__ A, const int* __restrict__ Bmat) {
    const int idx = blockIdx.x * 256 + threadIdx.x;
    const size_t base = (size_t)idx * 16;

    uint4 pa;
    {
        int4 v0 = *(const int4*)(A + base);
        int4 v1 = *(const int4*)(A + base + 4);
        int4 v2 = *(const int4*)(A + base + 8);
        int4 v3 = *(const int4*)(A + base + 12);
        pa.x = PACK4(v0); pa.y = PACK4(v1); pa.z = PACK4(v2); pa.w = PACK4(v3);
    }
    g_Apack[idx] = pa;

    uint4 pb;
    {
        int4 v0 = *(const int4*)(Bmat + base);
        int4 v1 = *(const int4*)(Bmat + base + 4);
        int4 v2 = *(const int4*)(Bmat + base + 8);
        int4 v3 = *(const int4*)(Bmat + base + 12);
        pb.x = PACK4(v0); pb.y = PACK4(v1); pb.z = PACK4(v2); pb.w = PACK4(v3);
    }
    g_Bpack[idx] = pb;
}

// ---------------- Main kernel ----------------
__global__ __launch_bounds__(256, 3)
void bmm_s8_main_kernel(const float* __restrict__ alpha_p,
                        float* __restrict__ Out) {
    __shared__ uint32_t As[BM * ROWSTRIDE];   // 18 KB
    __shared__ uint32_t Bs[BN * ROWSTRIDE];   //  9 KB

    const int tid  = threadIdx.x;
    const int lane = tid & 31;
    const int wid  = tid >> 5;

    const int bn = blockIdx.x;   // N block (16)
    const int bm = blockIdx.y;   // M block (8)
    const int bz = blockIdx.z;   // batch  (64)

    // ---- Load packed tiles ----
    {
        const uint4* Ab = g_Apack + ((size_t)bz * MDIM + bm * BM) * 8;
        #pragma unroll
        for (int i = 0; i < 4; i++) {
            int idx = tid + i * 256;
            int row = idx >> 3, qg = idx & 7;
            uint4 v = Ab[row * 8 + qg];
            *(uint4*)&As[row * ROWSTRIDE + qg * 4] = v;
        }
        const uint4* Bb = g_Bpack + ((size_t)bz * NDIM + bn * BN) * 8;
        #pragma unroll
        for (int i = 0; i < 2; i++) {
            int idx = tid + i * 256;
            int row = idx >> 3, qg = idx & 7;
            uint4 v = Bb[row * 8 + qg];
            *(uint4*)&Bs[row * ROWSTRIDE + qg * 4] = v;
        }
    }
    __syncthreads();

    const int rb = wid * 16;
    const int lr = lane & 3;     // mma thread-in-group
    const int lq = lane >> 2;    // mma group id
    const int g  = lane >> 3;    // dp4a row interleave 0..3
    const int j  = lane & 7;     // dp4a col interleave 0..7

    // ---- ldmatrix lane addresses ----
    const uint32_t a_lm = smem_u32(&As[(rb + (lane & 15)) * ROWSTRIDE
                                       + ((lane & 16) ? 4 : 0)]);
    const uint32_t b_lmP = smem_u32(&Bs[((lane & 7) + ((lane & 16) ? 8 : 0)) * ROWSTRIDE
                                        + ((lane & 8) ? 4 : 0)]);
    const uint32_t b_lm2 = smem_u32(&Bs[(32 + (lane & 7)) * ROWSTRIDE
                                        + ((lane & 8) ? 4 : 0)]);

    int macc[NI_MMA][4];
    #pragma unroll
    for (int ni = 0; ni < NI_MMA; ni++)
        #pragma unroll
        for (int r = 0; r < 4; r++) macc[ni][r] = 0;

    int dacc[4][NI_DP];
    #pragma unroll
    for (int mi = 0; mi < 4; mi++)
        #pragma unroll
        for (int ni = 0; ni < NI_DP; ni++) dacc[mi][ni] = 0;

    // --- IMMA block for one k-step ---
    #define IMMA_BLOCK(KS) do {                                                  \
        uint32_t af[4];                                                          \
        asm volatile("ldmatrix.sync.aligned.m8n8.x4.shared.b16 {%0,%1,%2,%3}, [%4];" \
                     : "=r"(af[0]), "=r"(af[1]), "=r"(af[2]), "=r"(af[3])        \
                     : "r"(a_lm + (KS) * 32));                                   \
        _Pragma("unroll")                                                        \
        for (int p = 0; p < 2; p++) {                                            \
            uint32_t bf[4];                                                      \
            asm volatile("ldmatrix.sync.aligned.m8n8.x4.shared.b16 {%0,%1,%2,%3}, [%4];" \
                         : "=r"(bf[0]), "=r"(bf[1]), "=r"(bf[2]), "=r"(bf[3])    \
                         : "r"(b_lmP + p * (16 * ROWSTRIDE * 4) + (KS) * 32));   \
            _Pragma("unroll")                                                    \
            for (int h = 0; h < 2; h++) {                                        \
                int ni = p * 2 + h;                                              \
                asm volatile(                                                    \
                    "mma.sync.aligned.m16n8k32.row.col.s32.s8.s8.s32 "           \
                    "{%0,%1,%2,%3}, {%4,%5,%6,%7}, {%8,%9}, {%0,%1,%2,%3};"      \
                    : "+r"(macc[ni][0]), "+r"(macc[ni][1]),                      \
                      "+r"(macc[ni][2]), "+r"(macc[ni][3])                       \
                    : "r"(af[0]), "r"(af[1]), "r"(af[2]), "r"(af[3]),            \
                      "r"(bf[h * 2]), "r"(bf[h * 2 + 1]));                       \
            }                                                                    \
        }                                                                        \
        {                                                                        \
            uint32_t bf[2];                                                      \
            asm volatile("ldmatrix.sync.aligned.m8n8.x2.shared.b16 {%0,%1}, [%2];" \
                         : "=r"(bf[0]), "=r"(bf[1])                              \
                         : "r"(b_lm2 + (KS) * 32));                              \
            asm volatile(                                                        \
                "mma.sync.aligned.m16n8k32.row.col.s32.s8.s8.s32 "               \
                "{%0,%1,%2,%3}, {%4,%5,%6,%7}, {%8,%9}, {%0,%1,%2,%3};"          \
                : "+r"(macc[4][0]), "+r"(macc[4][1]),                            \
                  "+r"(macc[4][2]), "+r"(macc[4][3])                             \
                : "r"(af[0]), "r"(af[1]), "r"(af[2]), "r"(af[3]),                \
                  "r"(bf[0]), "r"(bf[1]));                                       \
        }                                                                        \
    } while (0)

    // --- dp4a block for one k-step ---
    #define DP4A_BLOCK(KS) do {                                                  \
        _Pragma("unroll")                                                        \
        for (int c = 0; c < 2; c++) {                                            \
            const int kw = (KS) * 8 + c * 4;                                     \
            uint4 av[4];                                                         \
            _Pragma("unroll")                                                    \
            for (int mi = 0; mi < 4; mi++)                                       \
                av[mi] = *(const uint4*)&As[(rb + g + 4 * mi) * ROWSTRIDE + kw]; \
            _Pragma("unroll")                                                    \
            for (int ni = 0; ni < NI_DP; ni++) {                                 \
                uint4 bv = *(const uint4*)&Bs[(COL_DP + j + 8 * ni) * ROWSTRIDE + kw]; \
                _Pragma("unroll")                                                \
                for (int mi = 0; mi < 4; mi++) {                                 \
                    int v = dacc[mi][ni];                                        \
                    v = __dp4a((int)av[mi].x, (int)bv.x, v);                     \
                    v = __dp4a((int)av[mi].y, (int)bv.y, v);                     \
                    v = __dp4a((int)av[mi].z, (int)bv.z, v);                     \
                    v = __dp4a((int)av[mi].w, (int)bv.w, v);                     \
                    dacc[mi][ni] = v;                                            \
                }                                                                \
            }                                                                    \
        }                                                                        \
    } while (0)

    // Phase staggering: even warps IMMA->dp4a, odd warps dp4a->IMMA, so the
    // SM's tensor and fma/alu pipes are fed concurrently instead of in phases.
    if ((wid & 1) == 0) {
        #pragma unroll
        for (int ks = 0; ks < 4; ks++) { IMMA_BLOCK(ks); DP4A_BLOCK(ks); }
    } else {
        #pragma unroll
        for (int ks = 0; ks < 4; ks++) { DP4A_BLOCK(ks); IMMA_BLOCK(ks); }
    }
    #undef IMMA_BLOCK
    #undef DP4A_BLOCK

    // ---- Epilogue ----
    const float alpha = *alpha_p;
    float* obase = Out + ((size_t)bz * MDIM + (size_t)bm * BM) * NDIM + (size_t)bn * BN;

    #pragma unroll
    for (int ni = 0; ni < NI_MMA; ni++) {
        int c0 = ni * 8 + lr * 2;
        float2 v0;
        v0.x = __half2float(__float2half_rn(alpha * (float)macc[ni][0]));
        v0.y = __half2float(__float2half_rn(alpha * (float)macc[ni][1]));
        *(float2*)(obase + (size_t)(rb + lq) * NDIM + c0) = v0;
        float2 v1;
        v1.x = __half2float(__float2half_rn(alpha * (float)macc[ni][2]));
        v1.y = __half2float(__float2half_rn(alpha * (float)macc[ni][3]));
        *(float2*)(obase + (size_t)(rb + lq + 8) * NDIM + c0) = v1;
    }
    #pragma unroll
    for (int mi = 0; mi < 4; mi++) {
        float* orow = obase + (size_t)(rb + g + 4 * mi) * NDIM;
        #pragma unroll
        for (int ni = 0; ni < NI_DP; ni++) {
            int col = COL_DP + j + 8 * ni;
            orow[col] = __half2float(__float2half_rn(alpha * (float)dacc[mi][ni]));
        }
    }
}

extern "C" void kernel_launch(void* const* d_in, const int* in_sizes, int n_in,
                              void* d_out, int out_size) {
    // alpha is the size-1 input; the two large tensors are a then b in index order.
    int ai = -1, bi = -1, si = -1;
    for (int i = 0; i < n_in; i++) {
        if (in_sizes[i] == 1) { si = i; }
        else if (ai < 0)      { ai = i; }
        else                  { bi = i; }
    }
    const int*   a     = (const int*)d_in[ai];
    const int*   b     = (const int*)d_in[bi];
    const float* alpha = (const float*)d_in[si];
    float*       out   = (float*)d_out;

    pack_kernel<<<2048, 256>>>(a, b);

    dim3 grid(NDIM / BN, MDIM / BM, BATCH);   // (16, 8, 64)
    bmm_s8_main_kernel<<<grid, 256>>>(alpha, out);
}

// round 17
// speedup vs baseline: 1.2059x; 1.1234x over previous
#include <cuda_runtime.h>
#include <cuda_fp16.h>
#include <cstdint>

// BMM_S8T_S8N_F16T two-phase:
//  1) pack kernel: int32 inputs -> int8 packed scratch
//  2) main kernel: occ-3, CTA tile 128x64, asymmetric warp roles:
//     warps 0-3: IMMA, 32-row slab each, cols 0..39 (B fragments shared
//                across the two m16 row-blocks)
//     warps 4-7: dp4a, 32-row band each, cols 40..63 (mi=8, ni=3 thread
//                tiles -> fewer smem loads per MAC)
// out[b,m,n] = f32( fp16_round( alpha * sum_k a[b,m,k]*b[b,n,k] ) )

#define BATCH 64
#define MDIM 1024
#define NDIM 1024
#define KDIM 128

#define BM 128
#define BN 64
#define RS 36              // row stride words: 32 + 4 pad -> conflict-free

#define NI_MMA 5           // IMMA cols 0..39
#define COL_DP 40          // dp4a cols 40..63
#define NI_DP 3

__device__ uint4 g_Apack[(size_t)BATCH * MDIM * 8];
__device__ uint4 g_Bpack[(size_t)BATCH * NDIM * 8];

#define PACK4(v) __byte_perm(__byte_perm((v).x, (v).y, 0x0040), \
                             __byte_perm((v).z, (v).w, 0x0040), 0x5410)

static __device__ __forceinline__ uint32_t smem_u32(const void* p) {
    return (uint32_t)__cvta_generic_to_shared(p);
}

// ---------------- Pre-pass: pack int32 -> int8 ----------------
__global__ __launch_bounds__(256)
void pack_kernel(const int* __restrict__ A, const int* __restrict__ Bmat) {
    const int idx = blockIdx.x * 256 + threadIdx.x;
    const size_t base = (size_t)idx * 16;

    uint4 pa;
    {
        int4 v0 = __ldcs((const int4*)(A + base));
        int4 v1 = __ldcs((const int4*)(A + base + 4));
        int4 v2 = __ldcs((const int4*)(A + base + 8));
        int4 v3 = __ldcs((const int4*)(A + base + 12));
        pa.x = PACK4(v0); pa.y = PACK4(v1); pa.z = PACK4(v2); pa.w = PACK4(v3);
    }
    g_Apack[idx] = pa;

    uint4 pb;
    {
        int4 v0 = __ldcs((const int4*)(Bmat + base));
        int4 v1 = __ldcs((const int4*)(Bmat + base + 4));
        int4 v2 = __ldcs((const int4*)(Bmat + base + 8));
        int4 v3 = __ldcs((const int4*)(Bmat + base + 12));
        pb.x = PACK4(v0); pb.y = PACK4(v1); pb.z = PACK4(v2); pb.w = PACK4(v3);
    }
    g_Bpack[idx] = pb;
}

// ---------------- Main kernel ----------------
__global__ __launch_bounds__(256, 3)
void bmm_s8_main_kernel(const float* __restrict__ alpha_p,
                        float* __restrict__ Out) {
    __shared__ uint32_t As[BM * RS];   // 18 KB
    __shared__ uint32_t Bs[BN * RS];   //  9 KB

    const int tid  = threadIdx.x;
    const int lane = tid & 31;
    const int wid  = tid >> 5;

    const int bn = blockIdx.x;   // N block (16)
    const int bm = blockIdx.y;   // M block (8)
    const int bz = blockIdx.z;   // batch  (64)

    // ---- Load packed tiles ----
    {
        const uint4* Ab = g_Apack + ((size_t)bz * MDIM + bm * BM) * 8;
        #pragma unroll
        for (int i = 0; i < 4; i++) {
            int idx = tid + i * 256;
            int row = idx >> 3, qg = idx & 7;
            uint4 v = Ab[row * 8 + qg];
            *(uint4*)&As[row * RS + qg * 4] = v;
        }
        const uint4* Bb = g_Bpack + ((size_t)bz * NDIM + bn * BN) * 8;
        #pragma unroll
        for (int i = 0; i < 2; i++) {
            int idx = tid + i * 256;
            int row = idx >> 3, qg = idx & 7;
            uint4 v = Bb[row * 8 + qg];
            *(uint4*)&Bs[row * RS + qg * 4] = v;
        }
    }
    __syncthreads();

    const float alpha = *alpha_p;
    float* obase = Out + ((size_t)bz * MDIM + (size_t)bm * BM) * NDIM + (size_t)bn * BN;

    if (wid < 4) {
        // ============ IMMA warps: rows wid*32..+31, cols 0..39 ============
        const int rbI = wid * 32;
        const int lr = lane & 3;
        const int lq = lane >> 2;

        const uint32_t a_lm0 = smem_u32(&As[(rbI + (lane & 15)) * RS
                                            + ((lane & 16) ? 4 : 0)]);
        const uint32_t a_lm1 = a_lm0 + 16 * RS * 4;
        const uint32_t b_lmP = smem_u32(&Bs[((lane & 7) + ((lane & 16) ? 8 : 0)) * RS
                                            + ((lane & 8) ? 4 : 0)]);
        const uint32_t b_lm2 = smem_u32(&Bs[(32 + (lane & 7)) * RS
                                            + ((lane & 8) ? 4 : 0)]);

        int macc[2][NI_MMA][4];
        #pragma unroll
        for (int mi = 0; mi < 2; mi++)
            #pragma unroll
            for (int ni = 0; ni < NI_MMA; ni++)
                #pragma unroll
                for (int r = 0; r < 4; r++) macc[mi][ni][r] = 0;

        #pragma unroll
        for (int ks = 0; ks < 4; ks++) {
            uint32_t af[2][4];
            asm volatile("ldmatrix.sync.aligned.m8n8.x4.shared.b16 {%0,%1,%2,%3}, [%4];"
                         : "=r"(af[0][0]), "=r"(af[0][1]), "=r"(af[0][2]), "=r"(af[0][3])
                         : "r"(a_lm0 + ks * 32));
            asm volatile("ldmatrix.sync.aligned.m8n8.x4.shared.b16 {%0,%1,%2,%3}, [%4];"
                         : "=r"(af[1][0]), "=r"(af[1][1]), "=r"(af[1][2]), "=r"(af[1][3])
                         : "r"(a_lm1 + ks * 32));
            #pragma unroll
            for (int p = 0; p < 2; p++) {
                uint32_t bf[4];
                asm volatile("ldmatrix.sync.aligned.m8n8.x4.shared.b16 {%0,%1,%2,%3}, [%4];"
                             : "=r"(bf[0]), "=r"(bf[1]), "=r"(bf[2]), "=r"(bf[3])
                             : "r"(b_lmP + p * (16 * RS * 4) + ks * 32));
                #pragma unroll
                for (int h = 0; h < 2; h++) {
                    int ni = p * 2 + h;
                    #pragma unroll
                    for (int mi = 0; mi < 2; mi++) {
                        asm volatile(
                            "mma.sync.aligned.m16n8k32.row.col.s32.s8.s8.s32 "
                            "{%0,%1,%2,%3}, {%4,%5,%6,%7}, {%8,%9}, {%0,%1,%2,%3};"
                            : "+r"(macc[mi][ni][0]), "+r"(macc[mi][ni][1]),
                              "+r"(macc[mi][ni][2]), "+r"(macc[mi][ni][3])
                            : "r"(af[mi][0]), "r"(af[mi][1]), "r"(af[mi][2]), "r"(af[mi][3]),
                              "r"(bf[h * 2]), "r"(bf[h * 2 + 1]));
                    }
                }
            }
            {
                uint32_t bf[2];
                asm volatile("ldmatrix.sync.aligned.m8n8.x2.shared.b16 {%0,%1}, [%2];"
                             : "=r"(bf[0]), "=r"(bf[1]) : "r"(b_lm2 + ks * 32));
                #pragma unroll
                for (int mi = 0; mi < 2; mi++) {
                    asm volatile(
                        "mma.sync.aligned.m16n8k32.row.col.s32.s8.s8.s32 "
                        "{%0,%1,%2,%3}, {%4,%5,%6,%7}, {%8,%9}, {%0,%1,%2,%3};"
                        : "+r"(macc[mi][4][0]), "+r"(macc[mi][4][1]),
                          "+r"(macc[mi][4][2]), "+r"(macc[mi][4][3])
                        : "r"(af[mi][0]), "r"(af[mi][1]), "r"(af[mi][2]), "r"(af[mi][3]),
                          "r"(bf[0]), "r"(bf[1]));
                }
            }
        }

        // ---- IMMA epilogue ----
        #pragma unroll
        for (int mi = 0; mi < 2; mi++) {
            const int r0 = rbI + mi * 16 + lq;
            #pragma unroll
            for (int ni = 0; ni < NI_MMA; ni++) {
                int c0 = ni * 8 + lr * 2;
                float2 v0;
                v0.x = __half2float(__float2half_rn(alpha * (float)macc[mi][ni][0]));
                v0.y = __half2float(__float2half_rn(alpha * (float)macc[mi][ni][1]));
                *(float2*)(obase + (size_t)r0 * NDIM + c0) = v0;
                float2 v1;
                v1.x = __half2float(__float2half_rn(alpha * (float)macc[mi][ni][2]));
                v1.y = __half2float(__float2half_rn(alpha * (float)macc[mi][ni][3]));
                *(float2*)(obase + (size_t)(r0 + 8) * NDIM + c0) = v1;
            }
        }
    } else {
        // ============ dp4a warps: rows (wid-4)*32..+31, cols 40..63 ============
        const int band = (wid - 4) * 32;
        const int g = lane >> 3;   // 0..3
        const int j = lane & 7;    // 0..7

        int dacc[8][NI_DP];
        #pragma unroll
        for (int mi = 0; mi < 8; mi++)
            #pragma unroll
            for (int ni = 0; ni < NI_DP; ni++) dacc[mi][ni] = 0;

        #pragma unroll
        for (int gq = 0; gq < 8; gq++) {
            uint4 bv[NI_DP];
            #pragma unroll
            for (int ni = 0; ni < NI_DP; ni++)
                bv[ni] = *(const uint4*)&Bs[(COL_DP + j + 8 * ni) * RS + gq * 4];

            #pragma unroll
            for (int mh = 0; mh < 2; mh++) {
                uint4 av[4];
                #pragma unroll
                for (int mm = 0; mm < 4; mm++) {
                    int row = band + g + 4 * (mh * 4 + mm);
                    av[mm] = *(const uint4*)&As[row * RS + gq * 4];
                }
                #pragma unroll
                for (int ni = 0; ni < NI_DP; ni++) {
                    #pragma unroll
                    for (int mm = 0; mm < 4; mm++) {
                        int v = dacc[mh * 4 + mm][ni];
                        v = __dp4a((int)av[mm].x, (int)bv[ni].x, v);
                        v = __dp4a((int)av[mm].y, (int)bv[ni].y, v);
                        v = __dp4a((int)av[mm].z, (int)bv[ni].z, v);
                        v = __dp4a((int)av[mm].w, (int)bv[ni].w, v);
                        dacc[mh * 4 + mm][ni] = v;
                    }
                }
            }
        }

        // ---- dp4a epilogue ----
        #pragma unroll
        for (int mi = 0; mi < 8; mi++) {
            float* orow = obase + (size_t)(band + g + 4 * mi) * NDIM;
            #pragma unroll
            for (int ni = 0; ni < NI_DP; ni++) {
                int col = COL_DP + j + 8 * ni;
                orow[col] = __half2float(__float2half_rn(alpha * (float)dacc[mi][ni]));
            }
        }
    }
}

extern "C" void kernel_launch(void* const* d_in, const int* in_sizes, int n_in,
                              void* d_out, int out_size) {
    // alpha is the size-1 input; the two large tensors are a then b in index order.
    int ai = -1, bi = -1, si = -1;
    for (int i = 0; i < n_in; i++) {
        if (in_sizes[i] == 1) { si = i; }
        else if (ai < 0)      { ai = i; }
        else                  { bi = i; }
    }
    const int*   a     = (const int*)d_in[ai];
    const int*   b     = (const int*)d_in[bi];
    const float* alpha = (const float*)d_in[si];
    float*       out   = (float*)d_out;

    pack_kernel<<<2048, 256>>>(a, b);

    dim3 grid(NDIM / BN, MDIM / BM, BATCH);   // (16, 8, 64)
    bmm_s8_main_kernel<<<grid, 256>>>(alpha, out);
}